// round 3
// baseline (speedup 1.0000x reference)
#include <cuda_runtime.h>

#define N_NODES 50000
#define N_EDGES 800000
#define HDIM 128
#define DDIM 32
#define CDIM 64
#define RDIM 8

typedef unsigned long long ull;

// ---- scratch (device globals; no allocation in kernel_launch) ----
__device__ float g_t1[N_NODES * HDIM];          // silu(x)@W1+b1        [N,128]
__device__ float g_hbuf[N_NODES * DDIM];        // h                    [N,32]
__device__ float g_t2[N_NODES * RDIM * HDIM];   // silu(coeffs)@Wc1     [N*R,128]
__device__ float g_cbuf[N_NODES * RDIM * DDIM]; // c                    [N*R,32]
__device__ float g_agg[N_NODES * DDIM];         // segment_sum target   [N,32]

__device__ __forceinline__ float silu_f(float v) { return v / (1.0f + __expf(-v)); }

__device__ __forceinline__ ull fma2(ull a, ull b, ull c) {
    ull d;
    asm("fma.rn.f32x2 %0, %1, %2, %3;" : "=l"(d) : "l"(a), "l"(b), "l"(c));
    return d;
}

// Packed-f32x2 fused-silu GEMM: Y[M,NC] = act(A[M,K]) @ W[K,NC] (+bias)
// blockDim = (NC/4, TM/16). Per-thread tile: 8 row-pairs x 4 cols (64 MACs/k).
// A tile stored TRANSPOSED in smem (AsT[k][row]) -> LDS.64 yields a row-pair.
// W tile stored DUPLICATED (Wd[k][2c]=Wd[k][2c+1]=W[k][c]) -> LDS.64 yields a bcast pair.
template<int K, int KC, int NC, int TM, bool SILU, bool BIAS>
__global__ void __launch_bounds__((NC/4)*(TM/16)) gemm_f32x2_kernel(
    const float* __restrict__ A, const float* __restrict__ W,
    const float* __restrict__ bias, float* __restrict__ Y, int M)
{
    __shared__ __align__(16) float AsT[KC][TM + 2];
    __shared__ __align__(16) float Wd[KC][2 * NC];
    const int tx = threadIdx.x;                 // 0..NC/4-1  (cols tx + c*(NC/4))
    const int ty = threadIdx.y;                 // 0..TM/16-1 (row-pairs ty + p*(TM/16))
    const int TH = (NC/4) * (TM/16);
    const int tid = ty * (NC/4) + tx;
    const int m0 = blockIdx.x * TM;

    ull acc[8][4];
#pragma unroll
    for (int p = 0; p < 8; p++)
#pragma unroll
        for (int c = 0; c < 4; c++) acc[p][c] = 0ull;

    for (int k0 = 0; k0 < K; k0 += KC) {
        // A tile -> transposed smem, silu at load (each element touched once)
        for (int idx = tid; idx < TM * (KC/4); idx += TH) {
            int row = idx / (KC/4), cc = idx % (KC/4);
            float4 v = make_float4(0.f, 0.f, 0.f, 0.f);
            int m = m0 + row;
            if (m < M) v = *(const float4*)(A + (size_t)m * K + k0 + cc*4);
            if (SILU) { v.x = silu_f(v.x); v.y = silu_f(v.y); v.z = silu_f(v.z); v.w = silu_f(v.w); }
            AsT[cc*4+0][row] = v.x; AsT[cc*4+1][row] = v.y;
            AsT[cc*4+2][row] = v.z; AsT[cc*4+3][row] = v.w;
        }
        // W tile -> duplicated pairs
        for (int idx = tid; idx < KC * (NC/4); idx += TH) {
            int kk = idx / (NC/4), c4 = idx % (NC/4);
            float4 w = *(const float4*)(W + (size_t)(k0+kk) * NC + c4*4);
            *(float4*)&Wd[kk][c4*8 + 0] = make_float4(w.x, w.x, w.y, w.y);
            *(float4*)&Wd[kk][c4*8 + 4] = make_float4(w.z, w.z, w.w, w.w);
        }
        __syncthreads();
#pragma unroll 8
        for (int kk = 0; kk < KC; kk++) {
            ull wp[4], ap[8];
#pragma unroll
            for (int c = 0; c < 4; c++)
                wp[c] = *(const ull*)&Wd[kk][2 * (tx + c*(NC/4))];
#pragma unroll
            for (int p = 0; p < 8; p++)
                ap[p] = *(const ull*)&AsT[kk][2 * (ty + p*(TM/16))];
#pragma unroll
            for (int p = 0; p < 8; p++)
#pragma unroll
                for (int c = 0; c < 4; c++)
                    acc[p][c] = fma2(ap[p], wp[c], acc[p][c]);
        }
        __syncthreads();
    }

    float bv[4];
#pragma unroll
    for (int c = 0; c < 4; c++) bv[c] = BIAS ? bias[tx + c*(NC/4)] : 0.0f;

#pragma unroll
    for (int p = 0; p < 8; p++) {
        int m = m0 + 2 * (ty + p*(TM/16));
#pragma unroll
        for (int c = 0; c < 4; c++) {
            int col = tx + c*(NC/4);
            float2 v = *reinterpret_cast<float2*>(&acc[p][c]);
            if (m < M)     Y[(size_t)m * NC + col]       = v.x + bv[c];
            if (m + 1 < M) Y[(size_t)(m+1) * NC + col]   = v.y + bv[c];
        }
    }
}

// One warp per edge. Lane mapping: lane = r*4 + q ; each lane owns 8 d's.
__global__ void edge_kernel(const float* __restrict__ c, const float* __restrict__ h,
                            const float* __restrict__ rbfs, const int* __restrict__ ei,
                            float* __restrict__ agg)
{
    __shared__ float sw[8][32];
    int gwarp = blockIdx.x * 8 + (threadIdx.x >> 5);
    if (gwarp >= N_EDGES) return;
    int lane = threadIdx.x & 31;
    int r = lane >> 2, q = lane & 3;
    int src = ei[gwarp];
    int dst = ei[N_EDGES + gwarp];

    const float4* c4 = (const float4*)c;
    size_t bd = ((size_t)dst * RDIM + r) * 8 + q*2;
    size_t bs = ((size_t)src * RDIM + r) * 8 + q*2;
    float4 d0 = c4[bd], d1 = c4[bd+1];
    float4 s0 = c4[bs], s1 = c4[bs+1];

    float ce[8];
    ce[0] = d0.x * (s0.x + 1.0f); ce[1] = d0.y * (s0.y + 1.0f);
    ce[2] = d0.z * (s0.z + 1.0f); ce[3] = d0.w * (s0.w + 1.0f);
    ce[4] = d1.x * (s1.x + 1.0f); ce[5] = d1.y * (s1.y + 1.0f);
    ce[6] = d1.z * (s1.z + 1.0f); ce[7] = d1.w * (s1.w + 1.0f);

    float ss = 0.f;
#pragma unroll
    for (int i = 0; i < 8; i++) ss = fmaf(ce[i], ce[i], ss);
    ss += __shfl_xor_sync(0xffffffffu, ss, 1);
    ss += __shfl_xor_sync(0xffffffffu, ss, 2);
    float inv = rsqrtf(fmaxf(ss, 1e-24f));

    float scale = rbfs[(size_t)gwarp * RDIM + r] * inv;
    float w[8];
#pragma unroll
    for (int i = 0; i < 8; i++) w[i] = ce[i] * scale;

#pragma unroll
    for (int mask = 4; mask <= 16; mask <<= 1)
#pragma unroll
        for (int i = 0; i < 8; i++) w[i] += __shfl_xor_sync(0xffffffffu, w[i], mask);

    float ssw = 0.f;
#pragma unroll
    for (int i = 0; i < 8; i++) ssw = fmaf(w[i], w[i], ssw);
    ssw += __shfl_xor_sync(0xffffffffu, ssw, 1);
    ssw += __shfl_xor_sync(0xffffffffu, ssw, 2);
    float invw = rsqrtf(fmaxf(ssw, 1e-24f));

    int wib = threadIdx.x >> 5;
    if (r == 0) {
#pragma unroll
        for (int i = 0; i < 8; i++) sw[wib][q*8+i] = w[i];
    }
    __syncwarp();
    float wd = sw[wib][lane] * invw;
    float hd = h[(size_t)dst * DDIM + lane];
    atomicAdd(&agg[(size_t)src * DDIM + lane], hd * wd);
}

__global__ void zero_kernel(float4* p, int n4) {
    int i = blockIdx.x * blockDim.x + threadIdx.x;
    if (i < n4) p[i] = make_float4(0.f, 0.f, 0.f, 0.f);
}

extern "C" void kernel_launch(void* const* d_in, const int* in_sizes, int n_in,
                              void* d_out, int out_size)
{
    const float* x      = (const float*)d_in[0];
    const float* rbfs   = (const float*)d_in[1];
    const float* coeffs = (const float*)d_in[2];
    const float* W1     = (const float*)d_in[3];
    const float* b1     = (const float*)d_in[4];
    const float* W2     = (const float*)d_in[5];
    const float* b2     = (const float*)d_in[6];
    const float* Wc1    = (const float*)d_in[7];
    const float* Wc2    = (const float*)d_in[8];
    const float* Wu     = (const float*)d_in[9];
    const int*   ei     = (const int*)d_in[10];
    float* out = (float*)d_out;

    float *t1, *hbuf, *t2, *cbuf, *agg;
    cudaGetSymbolAddress((void**)&t1,   g_t1);
    cudaGetSymbolAddress((void**)&hbuf, g_hbuf);
    cudaGetSymbolAddress((void**)&t2,   g_t2);
    cudaGetSymbolAddress((void**)&cbuf, g_cbuf);
    cudaGetSymbolAddress((void**)&agg,  g_agg);

    const int MR = N_NODES * RDIM;

    // coeffs path: c = silu(silu(coeffs)@Wc1)@Wc2   (M = 400000)
    gemm_f32x2_kernel<64,16,128,128,true,false>
        <<<(MR + 127)/128, dim3(32,8)>>>(coeffs, Wc1, nullptr, t2, MR);
    gemm_f32x2_kernel<128,32,32,256,true,false>
        <<<(MR + 255)/256, dim3(8,16)>>>(t2, Wc2, nullptr, cbuf, MR);

    // node path: h = silu(silu(x)@W1+b1)@W2+b2
    gemm_f32x2_kernel<128,16,128,128,true,true>
        <<<(N_NODES + 127)/128, dim3(32,8)>>>(x, W1, b1, t1, N_NODES);
    gemm_f32x2_kernel<128,32,32,256,true,true>
        <<<(N_NODES + 255)/256, dim3(8,16)>>>(t1, W2, b2, hbuf, N_NODES);

    // zero aggregation buffer
    zero_kernel<<<((N_NODES*DDIM/4) + 255)/256, 256>>>((float4*)agg, N_NODES*DDIM/4);

    // edge stage + atomic segment-sum into agg
    edge_kernel<<<N_EDGES/8, 256>>>(cbuf, hbuf, rbfs, ei, agg);

    // out = agg @ Wu
    gemm_f32x2_kernel<32,16,128,128,false,false>
        <<<(N_NODES + 127)/128, dim3(32,8)>>>(agg, Wu, nullptr, out, N_NODES);
}

// round 4
// speedup vs baseline: 1.8786x; 1.8786x over previous
#include <cuda_runtime.h>
#include <cstdint>

#define N_NODES 50000
#define N_EDGES 800000
#define HDIM 128
#define DDIM 32
#define CDIM 64
#define RDIM 8

// ---- scratch (device globals; no allocation in kernel_launch) ----
__device__ float g_hbuf[N_NODES * DDIM];        // h                    [N,32]
__device__ float g_cbuf[N_NODES * RDIM * DDIM]; // c                    [N*R,32]
__device__ float g_agg[N_NODES * DDIM];         // segment_sum target   [N,32]

__device__ __forceinline__ float silu_f(float v) { return v / (1.0f + __expf(-v)); }

__device__ __forceinline__ uint32_t f2tf32(float f) {
    uint32_t u;
    asm("cvt.rna.tf32.f32 %0, %1;" : "=r"(u) : "f"(f));
    return u;
}

__device__ __forceinline__ void mma_tf32(float d[4], uint32_t a0, uint32_t a1,
                                         uint32_t a2, uint32_t a3,
                                         uint32_t b0, uint32_t b1) {
    asm volatile(
        "mma.sync.aligned.m16n8k8.row.col.f32.tf32.tf32.f32 "
        "{%0,%1,%2,%3},{%4,%5,%6,%7},{%8,%9},{%0,%1,%2,%3};"
        : "+f"(d[0]), "+f"(d[1]), "+f"(d[2]), "+f"(d[3])
        : "r"(a0), "r"(a1), "r"(a2), "r"(a3), "r"(b0), "r"(b1));
}

// Fused 2-layer MLP: Y[M,32] = silu(silu(A[M,K])@W1[K,128] (+b1)) @ W2[128,32] (+b2)
// 256 threads = 8 warps; warp w owns rows [blk*128 + w*16, +16).
// Phase-1 A-fragments straight from gmem (silu+tf32 in regs); intermediate H tile
// stored per-warp in smem as tf32; phase 2 reads it back as mma A-operand.
// Smem strides: W1s 136 (bank-perfect b-frag), C1s 132 (bank-perfect a-frag), W2s 40.
template<int K, bool BIAS>
__global__ void __launch_bounds__(256) fused_mlp_kernel(
    const float* __restrict__ A, const float* __restrict__ W1,
    const float* __restrict__ b1, const float* __restrict__ W2,
    const float* __restrict__ b2, float* __restrict__ Y, int M)
{
    extern __shared__ uint32_t sm[];
    uint32_t* W1s = sm;                        // [K][136] tf32
    uint32_t* C1s = W1s + K * 136;             // [128][132] tf32
    uint32_t* W2s = C1s + 128 * 132;           // [128][40] tf32
    float* b1s = (float*)(W2s + 128 * 40);     // [128]
    float* b2s = b1s + 128;                    // [32]

    const int tid = threadIdx.x;

    for (int i = tid; i < K * 128; i += 256) {
        int k = i >> 7, n = i & 127;
        W1s[k * 136 + n] = f2tf32(W1[i]);
    }
    for (int i = tid; i < 128 * 32; i += 256) {
        int k = i >> 5, n = i & 31;
        W2s[k * 40 + n] = f2tf32(W2[i]);
    }
    if (tid < 128) b1s[tid] = BIAS ? b1[tid] : 0.0f;
    if (tid < 32)  b2s[tid] = BIAS ? b2[tid] : 0.0f;
    __syncthreads();

    const int w = tid >> 5, lane = tid & 31;
    const int g = lane >> 2, tig = lane & 3;
    const int m0 = blockIdx.x * 128 + w * 16;
    const int r0 = m0 + g, r1 = m0 + g + 8;
    const bool v0 = r0 < M, v1 = r1 < M;

    // ---------------- phase 1: H = silu(A)@W1 ----------------
    float acc1[16][4];
#pragma unroll
    for (int nt = 0; nt < 16; nt++)
#pragma unroll
        for (int j = 0; j < 4; j++) acc1[nt][j] = 0.0f;

    const float* A0 = A + (size_t)r0 * K;
    const float* A1 = A + (size_t)r1 * K;

#pragma unroll
    for (int kt = 0; kt < K / 8; kt++) {
        const int c0 = kt * 8 + tig;
        float f0 = v0 ? A0[c0]     : 0.0f;
        float f1 = v1 ? A1[c0]     : 0.0f;
        float f2 = v0 ? A0[c0 + 4] : 0.0f;
        float f3 = v1 ? A1[c0 + 4] : 0.0f;
        uint32_t a0 = f2tf32(silu_f(f0));
        uint32_t a1 = f2tf32(silu_f(f1));
        uint32_t a2 = f2tf32(silu_f(f2));
        uint32_t a3 = f2tf32(silu_f(f3));
#pragma unroll
        for (int nt = 0; nt < 16; nt++) {
            uint32_t b0 = W1s[c0 * 136 + nt * 8 + g];
            uint32_t b1r = W1s[(c0 + 4) * 136 + nt * 8 + g];
            mma_tf32(acc1[nt], a0, a1, a2, a3, b0, b1r);
        }
    }

    // store H tile (bias + silu, as tf32) into this warp's private C1s rows
    const int row0 = w * 16 + g, row1 = w * 16 + g + 8;
#pragma unroll
    for (int nt = 0; nt < 16; nt++) {
        int cA = nt * 8 + 2 * tig;
        C1s[row0 * 132 + cA]     = f2tf32(silu_f(acc1[nt][0] + b1s[cA]));
        C1s[row0 * 132 + cA + 1] = f2tf32(silu_f(acc1[nt][1] + b1s[cA + 1]));
        C1s[row1 * 132 + cA]     = f2tf32(silu_f(acc1[nt][2] + b1s[cA]));
        C1s[row1 * 132 + cA + 1] = f2tf32(silu_f(acc1[nt][3] + b1s[cA + 1]));
    }
    __syncwarp();

    // ---------------- phase 2: Y = silu(H)@W2 ----------------
    float acc2[4][4];
#pragma unroll
    for (int nt = 0; nt < 4; nt++)
#pragma unroll
        for (int j = 0; j < 4; j++) acc2[nt][j] = 0.0f;

#pragma unroll
    for (int kt = 0; kt < 16; kt++) {
        const int c0 = kt * 8 + tig;
        uint32_t a0 = C1s[row0 * 132 + c0];
        uint32_t a1 = C1s[row1 * 132 + c0];
        uint32_t a2 = C1s[row0 * 132 + c0 + 4];
        uint32_t a3 = C1s[row1 * 132 + c0 + 4];
#pragma unroll
        for (int nt = 0; nt < 4; nt++) {
            uint32_t b0 = W2s[c0 * 40 + nt * 8 + g];
            uint32_t b1r = W2s[(c0 + 4) * 40 + nt * 8 + g];
            mma_tf32(acc2[nt], a0, a1, a2, a3, b0, b1r);
        }
    }

#pragma unroll
    for (int nt = 0; nt < 4; nt++) {
        int cA = nt * 8 + 2 * tig;
        if (v0) {
            Y[(size_t)r0 * 32 + cA]     = acc2[nt][0] + b2s[cA];
            Y[(size_t)r0 * 32 + cA + 1] = acc2[nt][1] + b2s[cA + 1];
        }
        if (v1) {
            Y[(size_t)r1 * 32 + cA]     = acc2[nt][2] + b2s[cA];
            Y[(size_t)r1 * 32 + cA + 1] = acc2[nt][3] + b2s[cA + 1];
        }
    }
}

// R1 FFMA GEMM (kept for the final up-projection): Y[M,NC] = A[M,K]@W[K,NC]
template<int K, int NC, int TM, bool SILU, bool BIAS>
__global__ void __launch_bounds__((NC/4)*(TM/8)) gemm_silu_kernel(
    const float* __restrict__ A, const float* __restrict__ W,
    const float* __restrict__ bias, float* __restrict__ Y, int M)
{
    __shared__ float As[TM][33];
    __shared__ float Ws[32][NC];
    const int tx = threadIdx.x;
    const int ty = threadIdx.y;
    const int TH = (NC/4)*(TM/8);
    const int tid = ty*(NC/4) + tx;
    const int m0 = blockIdx.x * TM;

    float acc[8][4];
#pragma unroll
    for (int i = 0; i < 8; i++)
#pragma unroll
        for (int j = 0; j < 4; j++) acc[i][j] = 0.0f;

    for (int k0 = 0; k0 < K; k0 += 32) {
        for (int idx = tid; idx < TM*8; idx += TH) {
            int row = idx >> 3, cc = idx & 7;
            float4 v = make_float4(0.f, 0.f, 0.f, 0.f);
            int m = m0 + row;
            if (m < M && (k0 + cc*4) < K) v = *(const float4*)(A + (size_t)m * K + k0 + cc*4);
            if (SILU) { v.x = silu_f(v.x); v.y = silu_f(v.y); v.z = silu_f(v.z); v.w = silu_f(v.w); }
            As[row][cc*4+0] = v.x; As[row][cc*4+1] = v.y;
            As[row][cc*4+2] = v.z; As[row][cc*4+3] = v.w;
        }
        for (int idx = tid; idx < 8*NC; idx += TH) {
            int kk = idx / (NC/4), cc = idx % (NC/4);
            float4 wv = make_float4(0.f,0.f,0.f,0.f);
            if (k0 + kk < K) wv = *(const float4*)(W + (size_t)(k0+kk)*NC + cc*4);
            *(float4*)&Ws[kk][cc*4] = wv;
        }
        __syncthreads();
#pragma unroll 8
        for (int kk = 0; kk < 32; kk++) {
            float4 wv = *(const float4*)&Ws[kk][tx*4];
#pragma unroll
            for (int i = 0; i < 8; i++) {
                float a = As[ty*8+i][kk];
                acc[i][0] = fmaf(a, wv.x, acc[i][0]);
                acc[i][1] = fmaf(a, wv.y, acc[i][1]);
                acc[i][2] = fmaf(a, wv.z, acc[i][2]);
                acc[i][3] = fmaf(a, wv.w, acc[i][3]);
            }
        }
        __syncthreads();
    }

    float4 bv = make_float4(0.f, 0.f, 0.f, 0.f);
    if (BIAS) bv = *(const float4*)(bias + tx*4);
#pragma unroll
    for (int i = 0; i < 8; i++) {
        int m = m0 + ty*8 + i;
        if (m < M) {
            float4 o = make_float4(acc[i][0]+bv.x, acc[i][1]+bv.y,
                                   acc[i][2]+bv.z, acc[i][3]+bv.w);
            *(float4*)(Y + (size_t)m * NC + tx*4) = o;
        }
    }
}

// One warp per edge. Lane mapping: lane = r*4 + q ; each lane owns 8 d's.
__global__ void edge_kernel(const float* __restrict__ c, const float* __restrict__ h,
                            const float* __restrict__ rbfs, const int* __restrict__ ei,
                            float* __restrict__ agg)
{
    __shared__ float sw[8][32];
    int gwarp = blockIdx.x * 8 + (threadIdx.x >> 5);
    if (gwarp >= N_EDGES) return;
    int lane = threadIdx.x & 31;
    int r = lane >> 2, q = lane & 3;
    int src = ei[gwarp];
    int dst = ei[N_EDGES + gwarp];

    const float4* c4 = (const float4*)c;
    size_t bd = ((size_t)dst * RDIM + r) * 8 + q*2;
    size_t bs = ((size_t)src * RDIM + r) * 8 + q*2;
    float4 d0 = c4[bd], d1 = c4[bd+1];
    float4 s0 = c4[bs], s1 = c4[bs+1];

    float ce[8];
    ce[0] = d0.x * (s0.x + 1.0f); ce[1] = d0.y * (s0.y + 1.0f);
    ce[2] = d0.z * (s0.z + 1.0f); ce[3] = d0.w * (s0.w + 1.0f);
    ce[4] = d1.x * (s1.x + 1.0f); ce[5] = d1.y * (s1.y + 1.0f);
    ce[6] = d1.z * (s1.z + 1.0f); ce[7] = d1.w * (s1.w + 1.0f);

    float ss = 0.f;
#pragma unroll
    for (int i = 0; i < 8; i++) ss = fmaf(ce[i], ce[i], ss);
    ss += __shfl_xor_sync(0xffffffffu, ss, 1);
    ss += __shfl_xor_sync(0xffffffffu, ss, 2);
    float inv = rsqrtf(fmaxf(ss, 1e-24f));

    float scale = rbfs[(size_t)gwarp * RDIM + r] * inv;
    float w[8];
#pragma unroll
    for (int i = 0; i < 8; i++) w[i] = ce[i] * scale;

#pragma unroll
    for (int mask = 4; mask <= 16; mask <<= 1)
#pragma unroll
        for (int i = 0; i < 8; i++) w[i] += __shfl_xor_sync(0xffffffffu, w[i], mask);

    float ssw = 0.f;
#pragma unroll
    for (int i = 0; i < 8; i++) ssw = fmaf(w[i], w[i], ssw);
    ssw += __shfl_xor_sync(0xffffffffu, ssw, 1);
    ssw += __shfl_xor_sync(0xffffffffu, ssw, 2);
    float invw = rsqrtf(fmaxf(ssw, 1e-24f));

    int wib = threadIdx.x >> 5;
    if (r == 0) {
#pragma unroll
        for (int i = 0; i < 8; i++) sw[wib][q*8+i] = w[i];
    }
    __syncwarp();
    float wd = sw[wib][lane] * invw;
    float hd = h[(size_t)dst * DDIM + lane];
    atomicAdd(&agg[(size_t)src * DDIM + lane], hd * wd);
}

__global__ void zero_kernel(float4* p, int n4) {
    int i = blockIdx.x * blockDim.x + threadIdx.x;
    if (i < n4) p[i] = make_float4(0.f, 0.f, 0.f, 0.f);
}

extern "C" void kernel_launch(void* const* d_in, const int* in_sizes, int n_in,
                              void* d_out, int out_size)
{
    const float* x      = (const float*)d_in[0];
    const float* rbfs   = (const float*)d_in[1];
    const float* coeffs = (const float*)d_in[2];
    const float* W1     = (const float*)d_in[3];
    const float* b1     = (const float*)d_in[4];
    const float* W2     = (const float*)d_in[5];
    const float* b2     = (const float*)d_in[6];
    const float* Wc1    = (const float*)d_in[7];
    const float* Wc2    = (const float*)d_in[8];
    const float* Wu     = (const float*)d_in[9];
    const int*   ei     = (const int*)d_in[10];
    float* out = (float*)d_out;

    float *hbuf, *cbuf, *agg;
    cudaGetSymbolAddress((void**)&hbuf, g_hbuf);
    cudaGetSymbolAddress((void**)&cbuf, g_cbuf);
    cudaGetSymbolAddress((void**)&agg,  g_agg);

    const int MR = N_NODES * RDIM;

    // dynamic smem sizes (bytes): K*136 + 128*132 + 128*40 + 160 words
    const int smem_c = (CDIM * 136 + 128 * 132 + 128 * 40 + 160) * 4;   // K=64
    const int smem_n = (HDIM * 136 + 128 * 132 + 128 * 40 + 160) * 4;   // K=128
    cudaFuncSetAttribute(fused_mlp_kernel<CDIM, false>,
                         cudaFuncAttributeMaxDynamicSharedMemorySize, smem_c);
    cudaFuncSetAttribute(fused_mlp_kernel<HDIM, true>,
                         cudaFuncAttributeMaxDynamicSharedMemorySize, smem_n);

    // coeffs path: c = silu(silu(coeffs)@Wc1)@Wc2   (M = 400000)
    fused_mlp_kernel<CDIM, false><<<(MR + 127) / 128, 256, smem_c>>>(
        coeffs, Wc1, nullptr, Wc2, nullptr, cbuf, MR);

    // node path: h = silu(silu(x)@W1+b1)@W2+b2
    fused_mlp_kernel<HDIM, true><<<(N_NODES + 127) / 128, 256, smem_n>>>(
        x, W1, b1, W2, b2, hbuf, N_NODES);

    // zero aggregation buffer
    zero_kernel<<<((N_NODES*DDIM/4) + 255)/256, 256>>>((float4*)agg, N_NODES*DDIM/4);

    // edge stage + atomic segment-sum into agg
    edge_kernel<<<N_EDGES/8, 256>>>(cbuf, hbuf, rbfs, ei, agg);

    // out = agg @ Wu
    gemm_silu_kernel<32,128,64,false,false>
        <<<(N_NODES + 63)/64, dim3(32,8)>>>(agg, Wu, nullptr, out, N_NODES);
}

// round 5
// speedup vs baseline: 2.0401x; 1.0859x over previous
#include <cuda_runtime.h>
#include <cstdint>

#define N_NODES 50000
#define N_EDGES 800000
#define HDIM 128
#define DDIM 32
#define CDIM 64
#define RDIM 8

// ---- scratch (device globals; no allocation in kernel_launch) ----
__device__ float g_hbuf[N_NODES * DDIM];        // h                    [N,32]
__device__ float g_cbuf[N_NODES * RDIM * DDIM]; // c                    [N*R,32]
__device__ float g_agg[N_NODES * DDIM];         // segment_sum target   [N,32]

__device__ __forceinline__ float silu_f(float v) { return v / (1.0f + __expf(-v)); }

__device__ __forceinline__ uint32_t f2tf32(float f) {
    uint32_t u;
    asm("cvt.rna.tf32.f32 %0, %1;" : "=r"(u) : "f"(f));
    return u;
}

__device__ __forceinline__ void mma_tf32(float d[4], uint32_t a0, uint32_t a1,
                                         uint32_t a2, uint32_t a3,
                                         uint32_t b0, uint32_t b1) {
    asm volatile(
        "mma.sync.aligned.m16n8k8.row.col.f32.tf32.tf32.f32 "
        "{%0,%1,%2,%3},{%4,%5,%6,%7},{%8,%9},{%0,%1,%2,%3};"
        : "+f"(d[0]), "+f"(d[1]), "+f"(d[2]), "+f"(d[3])
        : "r"(a0), "r"(a1), "r"(a2), "r"(a3), "r"(b0), "r"(b1));
}

__device__ __forceinline__ void red_v4(float* p, float4 v) {
    asm volatile("red.global.add.v4.f32 [%0], {%1,%2,%3,%4};"
                 :: "l"(p), "f"(v.x), "f"(v.y), "f"(v.z), "f"(v.w) : "memory");
}

// Fused 2-layer MLP: Y[M,32] = silu(silu(A[M,K])@W1[K,128] (+b1)) @ W2[128,32] (+b2)
// Grid-stride over 128-row tiles: W1/W2 converted to tf32 smem ONCE per block.
// 256 threads = 8 warps; warp w owns rows [tile*128 + w*16, +16).
// Phase-1 A operands prefetched fully into registers (batched LDGs) before mma.
template<int K, bool BIAS>
__global__ void __launch_bounds__(256) fused_mlp_kernel(
    const float* __restrict__ A, const float* __restrict__ W1,
    const float* __restrict__ b1, const float* __restrict__ W2,
    const float* __restrict__ b2, float* __restrict__ Y, int M)
{
    extern __shared__ uint32_t sm[];
    uint32_t* W1s = sm;                        // [K][136] tf32
    uint32_t* C1s = W1s + K * 136;             // [128][132] tf32 (per-warp private rows)
    uint32_t* W2s = C1s + 128 * 132;           // [128][40] tf32
    float* b1s = (float*)(W2s + 128 * 40);     // [128]
    float* b2s = b1s + 128;                    // [32]

    const int tid = threadIdx.x;

    for (int i = tid; i < K * 128; i += 256) {
        int k = i >> 7, n = i & 127;
        W1s[k * 136 + n] = f2tf32(W1[i]);
    }
    for (int i = tid; i < 128 * 32; i += 256) {
        int k = i >> 5, n = i & 31;
        W2s[k * 40 + n] = f2tf32(W2[i]);
    }
    if (tid < 128) b1s[tid] = BIAS ? b1[tid] : 0.0f;
    if (tid < 32)  b2s[tid] = BIAS ? b2[tid] : 0.0f;
    __syncthreads();

    const int w = tid >> 5, lane = tid & 31;
    const int g = lane >> 2, tig = lane & 3;
    const int row0 = w * 16 + g, row1 = w * 16 + g + 8;
    const int ntiles = (M + 127) / 128;

    for (int tile = blockIdx.x; tile < ntiles; tile += gridDim.x) {
        const int m0 = tile * 128 + w * 16;
        const int r0 = m0 + g, r1 = m0 + g + 8;
        const bool v0 = r0 < M, v1 = r1 < M;
        const float* A0 = A + (size_t)r0 * K;
        const float* A1 = A + (size_t)r1 * K;

        // prefetch + convert ALL phase-1 A fragments (batched LDGs, high MLP)
        uint32_t af[K / 8][4];
#pragma unroll
        for (int kt = 0; kt < K / 8; kt++) {
            const int c0 = kt * 8 + tig;
            float f0 = v0 ? A0[c0]     : 0.0f;
            float f1 = v1 ? A1[c0]     : 0.0f;
            float f2 = v0 ? A0[c0 + 4] : 0.0f;
            float f3 = v1 ? A1[c0 + 4] : 0.0f;
            af[kt][0] = f2tf32(silu_f(f0));
            af[kt][1] = f2tf32(silu_f(f1));
            af[kt][2] = f2tf32(silu_f(f2));
            af[kt][3] = f2tf32(silu_f(f3));
        }

        // ---------------- phase 1: H = silu(A)@W1 ----------------
        float acc1[16][4];
#pragma unroll
        for (int nt = 0; nt < 16; nt++)
#pragma unroll
            for (int j = 0; j < 4; j++) acc1[nt][j] = 0.0f;

#pragma unroll
        for (int kt = 0; kt < K / 8; kt++) {
            const int c0 = kt * 8 + tig;
#pragma unroll
            for (int nt = 0; nt < 16; nt++) {
                uint32_t b0  = W1s[c0 * 136 + nt * 8 + g];
                uint32_t b1r = W1s[(c0 + 4) * 136 + nt * 8 + g];
                mma_tf32(acc1[nt], af[kt][0], af[kt][1], af[kt][2], af[kt][3], b0, b1r);
            }
        }

        // store H tile (bias + silu, tf32) into this warp's private C1s rows
#pragma unroll
        for (int nt = 0; nt < 16; nt++) {
            int cA = nt * 8 + 2 * tig;
            C1s[row0 * 132 + cA]     = f2tf32(silu_f(acc1[nt][0] + b1s[cA]));
            C1s[row0 * 132 + cA + 1] = f2tf32(silu_f(acc1[nt][1] + b1s[cA + 1]));
            C1s[row1 * 132 + cA]     = f2tf32(silu_f(acc1[nt][2] + b1s[cA]));
            C1s[row1 * 132 + cA + 1] = f2tf32(silu_f(acc1[nt][3] + b1s[cA + 1]));
        }
        __syncwarp();

        // ---------------- phase 2: Y = silu(H)@W2 ----------------
        float acc2[4][4];
#pragma unroll
        for (int nt = 0; nt < 4; nt++)
#pragma unroll
            for (int j = 0; j < 4; j++) acc2[nt][j] = 0.0f;

#pragma unroll
        for (int kt = 0; kt < 16; kt++) {
            const int c0 = kt * 8 + tig;
            uint32_t a0 = C1s[row0 * 132 + c0];
            uint32_t a1 = C1s[row1 * 132 + c0];
            uint32_t a2 = C1s[row0 * 132 + c0 + 4];
            uint32_t a3 = C1s[row1 * 132 + c0 + 4];
#pragma unroll
            for (int nt = 0; nt < 4; nt++) {
                uint32_t b0  = W2s[c0 * 40 + nt * 8 + g];
                uint32_t b1r = W2s[(c0 + 4) * 40 + nt * 8 + g];
                mma_tf32(acc2[nt], a0, a1, a2, a3, b0, b1r);
            }
        }

#pragma unroll
        for (int nt = 0; nt < 4; nt++) {
            int cA = nt * 8 + 2 * tig;
            if (v0) {
                Y[(size_t)r0 * 32 + cA]     = acc2[nt][0] + b2s[cA];
                Y[(size_t)r0 * 32 + cA + 1] = acc2[nt][1] + b2s[cA + 1];
            }
            if (v1) {
                Y[(size_t)r1 * 32 + cA]     = acc2[nt][2] + b2s[cA];
                Y[(size_t)r1 * 32 + cA + 1] = acc2[nt][3] + b2s[cA + 1];
            }
        }
        __syncwarp();   // phase-2 reads done before next tile overwrites C1s
    }
}

// FFMA GEMM (final up-projection): Y[M,NC] = A[M,K]@W[K,NC]
template<int K, int NC, int TM, bool SILU, bool BIAS>
__global__ void __launch_bounds__((NC/4)*(TM/8)) gemm_silu_kernel(
    const float* __restrict__ A, const float* __restrict__ W,
    const float* __restrict__ bias, float* __restrict__ Y, int M)
{
    __shared__ float As[TM][33];
    __shared__ float Ws[32][NC];
    const int tx = threadIdx.x;
    const int ty = threadIdx.y;
    const int TH = (NC/4)*(TM/8);
    const int tid = ty*(NC/4) + tx;
    const int m0 = blockIdx.x * TM;

    float acc[8][4];
#pragma unroll
    for (int i = 0; i < 8; i++)
#pragma unroll
        for (int j = 0; j < 4; j++) acc[i][j] = 0.0f;

    for (int k0 = 0; k0 < K; k0 += 32) {
        for (int idx = tid; idx < TM*8; idx += TH) {
            int row = idx >> 3, cc = idx & 7;
            float4 v = make_float4(0.f, 0.f, 0.f, 0.f);
            int m = m0 + row;
            if (m < M && (k0 + cc*4) < K) v = *(const float4*)(A + (size_t)m * K + k0 + cc*4);
            if (SILU) { v.x = silu_f(v.x); v.y = silu_f(v.y); v.z = silu_f(v.z); v.w = silu_f(v.w); }
            As[row][cc*4+0] = v.x; As[row][cc*4+1] = v.y;
            As[row][cc*4+2] = v.z; As[row][cc*4+3] = v.w;
        }
        for (int idx = tid; idx < 8*NC; idx += TH) {
            int kk = idx / (NC/4), cc = idx % (NC/4);
            float4 wv = make_float4(0.f,0.f,0.f,0.f);
            if (k0 + kk < K) wv = *(const float4*)(W + (size_t)(k0+kk)*NC + cc*4);
            *(float4*)&Ws[kk][cc*4] = wv;
        }
        __syncthreads();
#pragma unroll 8
        for (int kk = 0; kk < 32; kk++) {
            float4 wv = *(const float4*)&Ws[kk][tx*4];
#pragma unroll
            for (int i = 0; i < 8; i++) {
                float a = As[ty*8+i][kk];
                acc[i][0] = fmaf(a, wv.x, acc[i][0]);
                acc[i][1] = fmaf(a, wv.y, acc[i][1]);
                acc[i][2] = fmaf(a, wv.z, acc[i][2]);
                acc[i][3] = fmaf(a, wv.w, acc[i][3]);
            }
        }
        __syncthreads();
    }

    float4 bv = make_float4(0.f, 0.f, 0.f, 0.f);
    if (BIAS) bv = *(const float4*)(bias + tx*4);
#pragma unroll
    for (int i = 0; i < 8; i++) {
        int m = m0 + ty*8 + i;
        if (m < M) {
            float4 o = make_float4(acc[i][0]+bv.x, acc[i][1]+bv.y,
                                   acc[i][2]+bv.z, acc[i][3]+bv.w);
            *(float4*)(Y + (size_t)m * NC + tx*4) = o;
        }
    }
}

// One warp per edge. Lane mapping: lane = r*4 + q ; each lane owns 8 d's.
// Tail: 4 lanes (r==0) emit 2x red.global.add.v4.f32 each (8 v4-REDG per edge).
__global__ void edge_kernel(const float* __restrict__ c, const float* __restrict__ h,
                            const float* __restrict__ rbfs, const int* __restrict__ ei,
                            float* __restrict__ agg)
{
    int gwarp = blockIdx.x * 8 + (threadIdx.x >> 5);
    if (gwarp >= N_EDGES) return;
    int lane = threadIdx.x & 31;
    int r = lane >> 2, q = lane & 3;
    int src = ei[gwarp];
    int dst = ei[N_EDGES + gwarp];

    const float4* c4 = (const float4*)c;
    size_t bd = ((size_t)dst * RDIM + r) * 8 + q*2;
    size_t bs = ((size_t)src * RDIM + r) * 8 + q*2;
    float4 d0 = c4[bd], d1 = c4[bd+1];
    float4 s0 = c4[bs], s1 = c4[bs+1];

    float ce[8];
    ce[0] = d0.x * (s0.x + 1.0f); ce[1] = d0.y * (s0.y + 1.0f);
    ce[2] = d0.z * (s0.z + 1.0f); ce[3] = d0.w * (s0.w + 1.0f);
    ce[4] = d1.x * (s1.x + 1.0f); ce[5] = d1.y * (s1.y + 1.0f);
    ce[6] = d1.z * (s1.z + 1.0f); ce[7] = d1.w * (s1.w + 1.0f);

    float ss = 0.f;
#pragma unroll
    for (int i = 0; i < 8; i++) ss = fmaf(ce[i], ce[i], ss);
    ss += __shfl_xor_sync(0xffffffffu, ss, 1);
    ss += __shfl_xor_sync(0xffffffffu, ss, 2);
    float inv = rsqrtf(fmaxf(ss, 1e-24f));

    float scale = rbfs[(size_t)gwarp * RDIM + r] * inv;
    float w[8];
#pragma unroll
    for (int i = 0; i < 8; i++) w[i] = ce[i] * scale;

#pragma unroll
    for (int mask = 4; mask <= 16; mask <<= 1)
#pragma unroll
        for (int i = 0; i < 8; i++) w[i] += __shfl_xor_sync(0xffffffffu, w[i], mask);

    float ssw = 0.f;
#pragma unroll
    for (int i = 0; i < 8; i++) ssw = fmaf(w[i], w[i], ssw);
    ssw += __shfl_xor_sync(0xffffffffu, ssw, 1);
    ssw += __shfl_xor_sync(0xffffffffu, ssw, 2);
    float invw = rsqrtf(fmaxf(ssw, 1e-24f));

    if (r == 0) {
        // lane q owns d = q*8 .. q*8+7 (w[] holds full r-sum; all r-copies identical)
        const float4* h4 = (const float4*)(h + (size_t)dst * DDIM + q * 8);
        float4 h0 = h4[0], h1 = h4[1];
        float* dstp = agg + (size_t)src * DDIM + q * 8;
        float4 m0 = make_float4(h0.x * w[0] * invw, h0.y * w[1] * invw,
                                h0.z * w[2] * invw, h0.w * w[3] * invw);
        float4 m1 = make_float4(h1.x * w[4] * invw, h1.y * w[5] * invw,
                                h1.z * w[6] * invw, h1.w * w[7] * invw);
        red_v4(dstp,     m0);
        red_v4(dstp + 4, m1);
    }
}

__global__ void zero_kernel(float4* p, int n4) {
    int i = blockIdx.x * blockDim.x + threadIdx.x;
    if (i < n4) p[i] = make_float4(0.f, 0.f, 0.f, 0.f);
}

extern "C" void kernel_launch(void* const* d_in, const int* in_sizes, int n_in,
                              void* d_out, int out_size)
{
    const float* x      = (const float*)d_in[0];
    const float* rbfs   = (const float*)d_in[1];
    const float* coeffs = (const float*)d_in[2];
    const float* W1     = (const float*)d_in[3];
    const float* b1     = (const float*)d_in[4];
    const float* W2     = (const float*)d_in[5];
    const float* b2     = (const float*)d_in[6];
    const float* Wc1    = (const float*)d_in[7];
    const float* Wc2    = (const float*)d_in[8];
    const float* Wu     = (const float*)d_in[9];
    const int*   ei     = (const int*)d_in[10];
    float* out = (float*)d_out;

    float *hbuf, *cbuf, *agg;
    cudaGetSymbolAddress((void**)&hbuf, g_hbuf);
    cudaGetSymbolAddress((void**)&cbuf, g_cbuf);
    cudaGetSymbolAddress((void**)&agg,  g_agg);

    const int MR = N_NODES * RDIM;

    const int smem_c = (CDIM * 136 + 128 * 132 + 128 * 40 + 160) * 4;   // K=64
    const int smem_n = (HDIM * 136 + 128 * 132 + 128 * 40 + 160) * 4;   // K=128
    cudaFuncSetAttribute(fused_mlp_kernel<CDIM, false>,
                         cudaFuncAttributeMaxDynamicSharedMemorySize, smem_c);
    cudaFuncSetAttribute(fused_mlp_kernel<HDIM, true>,
                         cudaFuncAttributeMaxDynamicSharedMemorySize, smem_n);

    // coeffs path: c = silu(silu(coeffs)@Wc1)@Wc2   (M = 400000; 148 persistent blocks)
    fused_mlp_kernel<CDIM, false><<<148, 256, smem_c>>>(
        coeffs, Wc1, nullptr, Wc2, nullptr, cbuf, MR);

    // node path: h = silu(silu(x)@W1+b1)@W2+b2
    fused_mlp_kernel<HDIM, true><<<148, 256, smem_n>>>(
        x, W1, b1, W2, b2, hbuf, N_NODES);

    // zero aggregation buffer
    zero_kernel<<<((N_NODES*DDIM/4) + 255)/256, 256>>>((float4*)agg, N_NODES*DDIM/4);

    // edge stage + v4 reduction segment-sum into agg
    edge_kernel<<<N_EDGES/8, 256>>>(cbuf, hbuf, rbfs, ei, agg);

    // out = agg @ Wu
    gemm_silu_kernel<32,128,64,false,false>
        <<<(N_NODES + 63)/64, dim3(32,8)>>>(agg, Wu, nullptr, out, N_NODES);
}

// round 6
// speedup vs baseline: 2.1768x; 1.0670x over previous
#include <cuda_runtime.h>
#include <cstdint>

#define N_NODES 50000
#define N_EDGES 800000
#define HDIM 128
#define DDIM 32
#define CDIM 64
#define RDIM 8

// ---- scratch (device globals; no allocation in kernel_launch) ----
__device__ float g_hbuf[N_NODES * DDIM];        // h                    [N,32]
__device__ float g_cbuf[N_NODES * RDIM * DDIM]; // c                    [N*R,32]
__device__ float g_agg[N_NODES * DDIM];         // segment_sum target   [N,32]

__device__ __forceinline__ float silu_f(float v) { return v / (1.0f + __expf(-v)); }

__device__ __forceinline__ uint32_t f2tf32(float f) {
    uint32_t u;
    asm("cvt.rna.tf32.f32 %0, %1;" : "=r"(u) : "f"(f));
    return u;
}

__device__ __forceinline__ void mma_tf32(float d[4], uint32_t a0, uint32_t a1,
                                         uint32_t a2, uint32_t a3,
                                         uint32_t b0, uint32_t b1) {
    asm volatile(
        "mma.sync.aligned.m16n8k8.row.col.f32.tf32.tf32.f32 "
        "{%0,%1,%2,%3},{%4,%5,%6,%7},{%8,%9},{%0,%1,%2,%3};"
        : "+f"(d[0]), "+f"(d[1]), "+f"(d[2]), "+f"(d[3])
        : "r"(a0), "r"(a1), "r"(a2), "r"(a3), "r"(b0), "r"(b1));
}

__device__ __forceinline__ void red_v4(float* p, float4 v) {
    asm volatile("red.global.add.v4.f32 [%0], {%1,%2,%3,%4};"
                 :: "l"(p), "f"(v.x), "f"(v.y), "f"(v.z), "f"(v.w) : "memory");
}

// Fused 2-layer MLP: Y[M,32] = silu(silu(A[M,K])@W1[K,128] (+b1)) @ W2[128,32] (+b2)
// Grid-stride over 128-row tiles: W1/W2 converted to tf32 smem ONCE per block.
// 256 threads = 8 warps; warp w owns rows [tile*128 + w*16, +16).
template<int K, bool BIAS>
__global__ void __launch_bounds__(256) fused_mlp_kernel(
    const float* __restrict__ A, const float* __restrict__ W1,
    const float* __restrict__ b1, const float* __restrict__ W2,
    const float* __restrict__ b2, float* __restrict__ Y, int M)
{
    extern __shared__ uint32_t sm[];
    uint32_t* W1s = sm;                        // [K][136] tf32
    uint32_t* C1s = W1s + K * 136;             // [128][132] tf32 (per-warp private rows)
    uint32_t* W2s = C1s + 128 * 132;           // [128][40] tf32
    float* b1s = (float*)(W2s + 128 * 40);     // [128]
    float* b2s = b1s + 128;                    // [32]

    const int tid = threadIdx.x;

    for (int i = tid; i < K * 128; i += 256) {
        int k = i >> 7, n = i & 127;
        W1s[k * 136 + n] = f2tf32(W1[i]);
    }
    for (int i = tid; i < 128 * 32; i += 256) {
        int k = i >> 5, n = i & 31;
        W2s[k * 40 + n] = f2tf32(W2[i]);
    }
    if (tid < 128) b1s[tid] = BIAS ? b1[tid] : 0.0f;
    if (tid < 32)  b2s[tid] = BIAS ? b2[tid] : 0.0f;
    __syncthreads();

    const int w = tid >> 5, lane = tid & 31;
    const int g = lane >> 2, tig = lane & 3;
    const int row0 = w * 16 + g, row1 = w * 16 + g + 8;
    const int ntiles = (M + 127) / 128;

    for (int tile = blockIdx.x; tile < ntiles; tile += gridDim.x) {
        const int m0 = tile * 128 + w * 16;
        const int r0 = m0 + g, r1 = m0 + g + 8;
        const bool v0 = r0 < M, v1 = r1 < M;
        const float* A0 = A + (size_t)r0 * K;
        const float* A1 = A + (size_t)r1 * K;

        // prefetch + convert ALL phase-1 A fragments (batched LDGs, high MLP)
        uint32_t af[K / 8][4];
#pragma unroll
        for (int kt = 0; kt < K / 8; kt++) {
            const int c0 = kt * 8 + tig;
            float f0 = v0 ? A0[c0]     : 0.0f;
            float f1 = v1 ? A1[c0]     : 0.0f;
            float f2 = v0 ? A0[c0 + 4] : 0.0f;
            float f3 = v1 ? A1[c0 + 4] : 0.0f;
            af[kt][0] = f2tf32(silu_f(f0));
            af[kt][1] = f2tf32(silu_f(f1));
            af[kt][2] = f2tf32(silu_f(f2));
            af[kt][3] = f2tf32(silu_f(f3));
        }

        // ---------------- phase 1: H = silu(A)@W1 ----------------
        float acc1[16][4];
#pragma unroll
        for (int nt = 0; nt < 16; nt++)
#pragma unroll
            for (int j = 0; j < 4; j++) acc1[nt][j] = 0.0f;

#pragma unroll
        for (int kt = 0; kt < K / 8; kt++) {
            const int c0 = kt * 8 + tig;
#pragma unroll
            for (int nt = 0; nt < 16; nt++) {
                uint32_t b0  = W1s[c0 * 136 + nt * 8 + g];
                uint32_t b1r = W1s[(c0 + 4) * 136 + nt * 8 + g];
                mma_tf32(acc1[nt], af[kt][0], af[kt][1], af[kt][2], af[kt][3], b0, b1r);
            }
        }

        // store H tile (bias + silu, tf32) into this warp's private C1s rows
#pragma unroll
        for (int nt = 0; nt < 16; nt++) {
            int cA = nt * 8 + 2 * tig;
            C1s[row0 * 132 + cA]     = f2tf32(silu_f(acc1[nt][0] + b1s[cA]));
            C1s[row0 * 132 + cA + 1] = f2tf32(silu_f(acc1[nt][1] + b1s[cA + 1]));
            C1s[row1 * 132 + cA]     = f2tf32(silu_f(acc1[nt][2] + b1s[cA]));
            C1s[row1 * 132 + cA + 1] = f2tf32(silu_f(acc1[nt][3] + b1s[cA + 1]));
        }
        __syncwarp();

        // ---------------- phase 2: Y = silu(H)@W2 ----------------
        float acc2[4][4];
#pragma unroll
        for (int nt = 0; nt < 4; nt++)
#pragma unroll
            for (int j = 0; j < 4; j++) acc2[nt][j] = 0.0f;

#pragma unroll
        for (int kt = 0; kt < 16; kt++) {
            const int c0 = kt * 8 + tig;
            uint32_t a0 = C1s[row0 * 132 + c0];
            uint32_t a1 = C1s[row1 * 132 + c0];
            uint32_t a2 = C1s[row0 * 132 + c0 + 4];
            uint32_t a3 = C1s[row1 * 132 + c0 + 4];
#pragma unroll
            for (int nt = 0; nt < 4; nt++) {
                uint32_t b0  = W2s[c0 * 40 + nt * 8 + g];
                uint32_t b1r = W2s[(c0 + 4) * 40 + nt * 8 + g];
                mma_tf32(acc2[nt], a0, a1, a2, a3, b0, b1r);
            }
        }

#pragma unroll
        for (int nt = 0; nt < 4; nt++) {
            int cA = nt * 8 + 2 * tig;
            if (v0) {
                Y[(size_t)r0 * 32 + cA]     = acc2[nt][0] + b2s[cA];
                Y[(size_t)r0 * 32 + cA + 1] = acc2[nt][1] + b2s[cA + 1];
            }
            if (v1) {
                Y[(size_t)r1 * 32 + cA]     = acc2[nt][2] + b2s[cA];
                Y[(size_t)r1 * 32 + cA + 1] = acc2[nt][3] + b2s[cA + 1];
            }
        }
        __syncwarp();   // phase-2 reads done before next tile overwrites C1s
    }
}

// FFMA GEMM (final up-projection): Y[M,NC] = A[M,K]@W[K,NC]
template<int K, int NC, int TM, bool SILU, bool BIAS>
__global__ void __launch_bounds__((NC/4)*(TM/8)) gemm_silu_kernel(
    const float* __restrict__ A, const float* __restrict__ W,
    const float* __restrict__ bias, float* __restrict__ Y, int M)
{
    __shared__ float As[TM][33];
    __shared__ float Ws[32][NC];
    const int tx = threadIdx.x;
    const int ty = threadIdx.y;
    const int TH = (NC/4)*(TM/8);
    const int tid = ty*(NC/4) + tx;
    const int m0 = blockIdx.x * TM;

    float acc[8][4];
#pragma unroll
    for (int i = 0; i < 8; i++)
#pragma unroll
        for (int j = 0; j < 4; j++) acc[i][j] = 0.0f;

    for (int k0 = 0; k0 < K; k0 += 32) {
        for (int idx = tid; idx < TM*8; idx += TH) {
            int row = idx >> 3, cc = idx & 7;
            float4 v = make_float4(0.f, 0.f, 0.f, 0.f);
            int m = m0 + row;
            if (m < M && (k0 + cc*4) < K) v = *(const float4*)(A + (size_t)m * K + k0 + cc*4);
            if (SILU) { v.x = silu_f(v.x); v.y = silu_f(v.y); v.z = silu_f(v.z); v.w = silu_f(v.w); }
            As[row][cc*4+0] = v.x; As[row][cc*4+1] = v.y;
            As[row][cc*4+2] = v.z; As[row][cc*4+3] = v.w;
        }
        for (int idx = tid; idx < 8*NC; idx += TH) {
            int kk = idx / (NC/4), cc = idx % (NC/4);
            float4 wv = make_float4(0.f,0.f,0.f,0.f);
            if (k0 + kk < K) wv = *(const float4*)(W + (size_t)(k0+kk)*NC + cc*4);
            *(float4*)&Ws[kk][cc*4] = wv;
        }
        __syncthreads();
#pragma unroll 8
        for (int kk = 0; kk < 32; kk++) {
            float4 wv = *(const float4*)&Ws[kk][tx*4];
#pragma unroll
            for (int i = 0; i < 8; i++) {
                float a = As[ty*8+i][kk];
                acc[i][0] = fmaf(a, wv.x, acc[i][0]);
                acc[i][1] = fmaf(a, wv.y, acc[i][1]);
                acc[i][2] = fmaf(a, wv.z, acc[i][2]);
                acc[i][3] = fmaf(a, wv.w, acc[i][3]);
            }
        }
        __syncthreads();
    }

    float4 bv = make_float4(0.f, 0.f, 0.f, 0.f);
    if (BIAS) bv = *(const float4*)(bias + tx*4);
#pragma unroll
    for (int i = 0; i < 8; i++) {
        int m = m0 + ty*8 + i;
        if (m < M) {
            float4 o = make_float4(acc[i][0]+bv.x, acc[i][1]+bv.y,
                                   acc[i][2]+bv.z, acc[i][3]+bv.w);
            *(float4*)(Y + (size_t)m * NC + tx*4) = o;
        }
    }
}

// One warp per edge, fully-coalesced c loads.
// Lane l reads float4 #l and #(32+l) of each 256-float c row (2 contiguous
// 512B sweeps per row -> 4 L1 lines per LDG.128 instead of 8).
// Lane l owns cols colA = 4*(l&7)..+3 of rA = l>>3 (chunk A) and rB = rA+4 (chunk B).
__global__ void edge_kernel(const float* __restrict__ c, const float* __restrict__ h,
                            const float* __restrict__ rbfs, const int* __restrict__ ei,
                            float* __restrict__ agg)
{
    int gwarp = blockIdx.x * 8 + (threadIdx.x >> 5);
    if (gwarp >= N_EDGES) return;
    const int lane = threadIdx.x & 31;
    const int grp = lane >> 3;          // rA = grp, rB = grp+4
    const int col4 = lane & 7;          // owns cols col4*4 .. col4*4+3

    const int src = ei[gwarp];
    const int dst = ei[N_EDGES + gwarp];

    const float4* c4 = (const float4*)c;
    const size_t db = (size_t)dst * 64;     // row = 256 floats = 64 float4
    const size_t sb = (size_t)src * 64;
    float4 d0 = c4[db + lane], d1 = c4[db + 32 + lane];
    float4 s0 = c4[sb + lane], s1 = c4[sb + 32 + lane];

    float ceA[4], ceB[4];
    ceA[0] = d0.x * (s0.x + 1.0f); ceA[1] = d0.y * (s0.y + 1.0f);
    ceA[2] = d0.z * (s0.z + 1.0f); ceA[3] = d0.w * (s0.w + 1.0f);
    ceB[0] = d1.x * (s1.x + 1.0f); ceB[1] = d1.y * (s1.y + 1.0f);
    ceB[2] = d1.z * (s1.z + 1.0f); ceB[3] = d1.w * (s1.w + 1.0f);

    // per-r sumsq over the 8 lanes of each group (masks 1,2,4), both r's packed
    float ssA = 0.f, ssB = 0.f;
#pragma unroll
    for (int j = 0; j < 4; j++) { ssA = fmaf(ceA[j], ceA[j], ssA); ssB = fmaf(ceB[j], ceB[j], ssB); }
#pragma unroll
    for (int mask = 1; mask <= 4; mask <<= 1) {
        ssA += __shfl_xor_sync(0xffffffffu, ssA, mask);
        ssB += __shfl_xor_sync(0xffffffffu, ssB, mask);
    }
    float invA = rsqrtf(fmaxf(ssA, 1e-24f));
    float invB = rsqrtf(fmaxf(ssB, 1e-24f));

    // rbf: one 8-lane load + 2 shuffles
    float rv = (lane < 8) ? rbfs[(size_t)gwarp * RDIM + lane] : 0.0f;
    float rbA = __shfl_sync(0xffffffffu, rv, grp);
    float rbB = __shfl_sync(0xffffffffu, rv, grp + 4);

    float sA = rbA * invA, sB = rbB * invB;
    // local combine (rA and rB contribute to the SAME cols), then reduce over
    // the 4 lane-groups (masks 8,16) -> full sum over all 8 r's
    float wl[4];
#pragma unroll
    for (int j = 0; j < 4; j++) wl[j] = ceA[j] * sA + ceB[j] * sB;
#pragma unroll
    for (int mask = 8; mask <= 16; mask <<= 1)
#pragma unroll
        for (int j = 0; j < 4; j++) wl[j] += __shfl_xor_sync(0xffffffffu, wl[j], mask);

    // w-norm over the 8 distinct col-groups (masks 1,2,4)
    float sq = 0.f;
#pragma unroll
    for (int j = 0; j < 4; j++) sq = fmaf(wl[j], wl[j], sq);
#pragma unroll
    for (int mask = 1; mask <= 4; mask <<= 1)
        sq += __shfl_xor_sync(0xffffffffu, sq, mask);
    float invw = rsqrtf(fmaxf(sq, 1e-24f));

    if (grp == 0) {
        // lanes 0..7: one contiguous 128B h load + one contiguous 128B v4-reduce
        const float4 hv = *(const float4*)(h + (size_t)dst * DDIM + col4 * 4);
        float4 m = make_float4(hv.x * wl[0] * invw, hv.y * wl[1] * invw,
                               hv.z * wl[2] * invw, hv.w * wl[3] * invw);
        red_v4(agg + (size_t)src * DDIM + col4 * 4, m);
    }
}

__global__ void zero_kernel(float4* p, int n4) {
    int i = blockIdx.x * blockDim.x + threadIdx.x;
    if (i < n4) p[i] = make_float4(0.f, 0.f, 0.f, 0.f);
}

extern "C" void kernel_launch(void* const* d_in, const int* in_sizes, int n_in,
                              void* d_out, int out_size)
{
    const float* x      = (const float*)d_in[0];
    const float* rbfs   = (const float*)d_in[1];
    const float* coeffs = (const float*)d_in[2];
    const float* W1     = (const float*)d_in[3];
    const float* b1     = (const float*)d_in[4];
    const float* W2     = (const float*)d_in[5];
    const float* b2     = (const float*)d_in[6];
    const float* Wc1    = (const float*)d_in[7];
    const float* Wc2    = (const float*)d_in[8];
    const float* Wu     = (const float*)d_in[9];
    const int*   ei     = (const int*)d_in[10];
    float* out = (float*)d_out;

    float *hbuf, *cbuf, *agg;
    cudaGetSymbolAddress((void**)&hbuf, g_hbuf);
    cudaGetSymbolAddress((void**)&cbuf, g_cbuf);
    cudaGetSymbolAddress((void**)&agg,  g_agg);

    const int MR = N_NODES * RDIM;

    const int smem_c = (CDIM * 136 + 128 * 132 + 128 * 40 + 160) * 4;   // K=64
    const int smem_n = (HDIM * 136 + 128 * 132 + 128 * 40 + 160) * 4;   // K=128
    cudaFuncSetAttribute(fused_mlp_kernel<CDIM, false>,
                         cudaFuncAttributeMaxDynamicSharedMemorySize, smem_c);
    cudaFuncSetAttribute(fused_mlp_kernel<HDIM, true>,
                         cudaFuncAttributeMaxDynamicSharedMemorySize, smem_n);

    // coeffs path: c = silu(silu(coeffs)@Wc1)@Wc2   (M = 400000; 148 persistent blocks)
    fused_mlp_kernel<CDIM, false><<<148, 256, smem_c>>>(
        coeffs, Wc1, nullptr, Wc2, nullptr, cbuf, MR);

    // node path: h = silu(silu(x)@W1+b1)@W2+b2
    fused_mlp_kernel<HDIM, true><<<148, 256, smem_n>>>(
        x, W1, b1, W2, b2, hbuf, N_NODES);

    // zero aggregation buffer
    zero_kernel<<<((N_NODES*DDIM/4) + 255)/256, 256>>>((float4*)agg, N_NODES*DDIM/4);

    // edge stage + v4 reduction segment-sum into agg
    edge_kernel<<<N_EDGES/8, 256>>>(cbuf, hbuf, rbfs, ei, agg);

    // out = agg @ Wu
    gemm_silu_kernel<32,128,64,false,false>
        <<<(N_NODES + 63)/64, dim3(32,8)>>>(agg, Wu, nullptr, out, N_NODES);
}